// round 14
// baseline (speedup 1.0000x reference)
#include <cuda_runtime.h>
#include <cuda_fp16.h>
#include <cstdint>
#include <cfloat>

// Problem constants
#define NN 65536
#define DD 128
#define MM 8
#define KK 256

#define BM      128
#define THREADS 512            // 16 warps: wr = wid&3 (32-row group), wc = wid>>2 (64-col strip)

// fp16 tile row stride: 136 elems = 272B; 272 % 128 = 16 -> ldmatrix conflict-free
#define ROWB 272

// smem layout (byte offsets)
#define SM_CB    0                       // 256*272 = 69632
#define SM_RB    69632                   // 128*272 = 34816
#define SM_REC   104448                  // recon fp32: 128*128*4 = 65536
#define SM_CSQ   169984                  // 1024
#define SM_RSS   171008                  // 512
#define SM_MIN1  171520                  // 128*4*8 = 4096
#define SM_MIN2  175616                  // 4096
#define SM_BESTK 179712                  // 1024
#define SM_NEED  180736                  // 512
#define SM_BYTES 181248                  // 177 KB -> 1 CTA/SM

__device__ float g_csq[MM][KK];
__device__ float g_cmax[MM];
// transposed fp32 codebooks: g_cbT[st][d][k] (1MB, L2-resident) -> coalesced rescue
__device__ float g_cbT[(size_t)MM * DD * KK];
// fp16 codebook pre-packed in the exact padded smem image -> cp.async straight in
__device__ __align__(16) char g_cbH[MM][(size_t)KK * ROWB];

__device__ __forceinline__ uint32_t ford(float f) {
    uint32_t u = __float_as_uint(f);
    return (u & 0x80000000u) ? ~u : (u | 0x80000000u);
}
__device__ __forceinline__ float unford(uint32_t e) {
    return __uint_as_float((e & 0x80000000u) ? (e & 0x7fffffffu) : ~e);
}
__device__ __forceinline__ uint32_t smem_u32(const void* p) {
    uint32_t a;
    asm("{ .reg .u64 t; cvta.to.shared.u64 t, %1; cvt.u32.u64 %0, t; }" : "=r"(a) : "l"(p));
    return a;
}
__device__ __forceinline__ void cp_async16(uint32_t dst, const void* src) {
    asm volatile("cp.async.ca.shared.global [%0], [%1], 16;" :: "r"(dst), "l"(src));
}
__device__ __forceinline__ void cp_async_wait_all() {
    asm volatile("cp.async.commit_group;\n\tcp.async.wait_group 0;" ::: "memory");
}
__device__ __forceinline__ void ldm_x4(uint32_t& r0, uint32_t& r1, uint32_t& r2,
                                       uint32_t& r3, uint32_t addr) {
    asm volatile("ldmatrix.sync.aligned.m8n8.x4.shared.b16 {%0,%1,%2,%3}, [%4];"
                 : "=r"(r0), "=r"(r1), "=r"(r2), "=r"(r3) : "r"(addr));
}
__device__ __forceinline__ void mma_f16(float& c0, float& c1, float& c2, float& c3,
                                        uint32_t a0, uint32_t a1, uint32_t a2, uint32_t a3,
                                        uint32_t b0, uint32_t b1) {
    asm volatile("mma.sync.aligned.m16n8k16.row.col.f32.f16.f16.f32 "
                 "{%0,%1,%2,%3}, {%4,%5,%6,%7}, {%8,%9}, {%0,%1,%2,%3};"
                 : "+f"(c0), "+f"(c1), "+f"(c2), "+f"(c3)
                 : "r"(a0), "r"(a1), "r"(a2), "r"(a3), "r"(b0), "r"(b1));
}
__device__ __forceinline__ void upd2(unsigned long long& b1, unsigned long long& b2,
                                     unsigned long long k) {
    if (k < b1) { b2 = b1; b1 = k; }
    else if (k < b2) b2 = k;
}
__device__ __forceinline__ void mrg2(unsigned long long& b1, unsigned long long& b2,
                                     unsigned long long o1, unsigned long long o2) {
    if (o1 < b1) { b2 = (b1 < o2) ? b1 : o2; b1 = o1; }
    else         { b2 = (b2 < o1) ? b2 : o1; }
}

__global__ void csq_prep_kernel(const float* __restrict__ cb) {
    int st = blockIdx.x;
    int k  = threadIdx.x;                  // 256 threads
    const float* row = cb + ((size_t)st * KK + k) * DD;
    float s = 0.f;
    for (int d = 0; d < DD; ++d) { float v = row[d]; s = fmaf(v, v, s); }
    g_csq[st][k] = s;
    __shared__ float red[KK];
    red[k] = s;
    __syncthreads();
    for (int off = 128; off > 0; off >>= 1) {
        if (k < off) red[k] = fmaxf(red[k], red[k + off]);
        __syncthreads();
    }
    if (k == 0) g_cmax[st] = sqrtf(red[0]);
}

// one-shot transpose: g_cbT[st][d][k] = cb[st][k][d]
__global__ void cbt_prep_kernel(const float* __restrict__ cb) {
    int st = blockIdx.x, d = blockIdx.y;
    int k  = threadIdx.x;                  // 256 threads
    g_cbT[((size_t)st * DD + d) * KK + k] = cb[((size_t)st * KK + k) * DD + d];
}

// one-shot fp16 pack in padded smem image (row k at byte k*ROWB, padding zeroed)
__global__ void cbh_prep_kernel(const float* __restrict__ cb) {
    int st = blockIdx.x;
    int k  = threadIdx.x;                  // 256 threads, one codeword row each
    const float* row = cb + ((size_t)st * KK + k) * DD;
    char* dst = g_cbH[st] + (size_t)k * ROWB;
    for (int dp = 0; dp < 64; ++dp) {
        float2 v = *(const float2*)(row + dp * 2);
        __half2 h = __floats2half2_rn(v.x, v.y);
        *(uint32_t*)(dst + dp * 4) = *(uint32_t*)&h;
    }
    for (int j = 0; j < 4; ++j) *(uint32_t*)(dst + 256 + j * 4) = 0u;  // padding
}

// ---- fused: all 8 stages in one kernel; recon tile lives in smem ----
__global__ __launch_bounds__(THREADS, 1)
void rq_fused_kernel(const float* __restrict__ x,
                     const float* __restrict__ cb,      // (M, K, D) fp32
                     float* __restrict__ codes,
                     float* __restrict__ side,          // (M, N, D)
                     float* __restrict__ xrecon)
{
    extern __shared__ char smem[];
    const uint32_t sbase = smem_u32(smem);
    float* csq  = (float*)(smem + SM_CSQ);
    float* rss  = (float*)(smem + SM_RSS);
    float* rec  = (float*)(smem + SM_REC);               // recon[r][d], stride 128
    unsigned long long* min1  = (unsigned long long*)(smem + SM_MIN1);
    unsigned long long* min2  = (unsigned long long*)(smem + SM_MIN2);
    unsigned long long* bestk = (unsigned long long*)(smem + SM_BESTK);
    int* need = (int*)(smem + SM_NEED);

    const int tid  = threadIdx.x;
    const int wid  = tid >> 5;
    const int lane = tid & 31;
    const int rowBase = blockIdx.x * BM;

    // zero recon tile
    #pragma unroll 4
    for (int i = tid; i < BM * DD / 4; i += THREADS)
        ((float4*)rec)[i] = make_float4(0.f, 0.f, 0.f, 0.f);
    __syncthreads();

    const int wr = wid & 3;
    const int wc = wid >> 2;                // 0..3: 64-col strip
    const int m_base  = wr * 32;
    const int n_base0 = wc * 64;
    const int qr = lane >> 2;
    const int qc = (lane & 3) * 2;
    const uint32_t aOff = (uint32_t)(((lane & 7) + ((lane >> 3) & 1) * 8 + m_base) * ROWB
                                     + ((lane >> 4) & 1) * 16);
    const uint32_t bOff = (uint32_t)(((lane & 7) + ((lane >> 4) & 1) * 8) * ROWB
                                     + ((lane >> 3) & 1) * 16);
    const uint32_t rbT = sbase + SM_RB, cbS = sbase + SM_CB;

    #pragma unroll 1
    for (int stage = 0; stage < MM; ++stage) {
        const float* C   = cb + (size_t)stage * KK * DD;
        const int    last = (stage == MM - 1);

        // ---- codebook fp16 tile via cp.async (overlaps with residual prep) ----
        {
            const char* src = g_cbH[stage];
            #pragma unroll
            for (int j = 0; j < 9; ++j) {
                int c16 = tid + j * THREADS;        // 4352 chunks of 16B
                if (c16 < (KK * ROWB) / 16)
                    cp_async16(sbase + SM_CB + c16 * 16, src + (size_t)c16 * 16);
            }
        }
        if (tid < KK) csq[tid] = g_csq[stage][tid];

        // ---- residual = x - recon -> fp16 tile + exact fp32 rss ----
        {
            int r  = tid >> 2;
            int c0 = (tid & 3) * 32;
            const float* xrow = x + (size_t)(rowBase + r) * DD + c0;
            const float* rrow = rec + r * DD + c0;
            float part = 0.f;
            #pragma unroll 4
            for (int j = 0; j < 32; j += 4) {
                float4 xv = *(const float4*)(xrow + j);
                float4 pv = *(const float4*)(rrow + j);
                float r0 = xv.x - pv.x, r1 = xv.y - pv.y;
                float r2 = xv.z - pv.z, r3 = xv.w - pv.w;
                __half2 h0 = __floats2half2_rn(r0, r1);
                __half2 h1 = __floats2half2_rn(r2, r3);
                uint2 pk = make_uint2(*(uint32_t*)&h0, *(uint32_t*)&h1);
                *(uint2*)(smem + SM_RB + r * ROWB + (c0 + j) * 2) = pk;
                part = fmaf(r0, r0, part); part = fmaf(r1, r1, part);
                part = fmaf(r2, r2, part); part = fmaf(r3, r3, part);
            }
            part += __shfl_xor_sync(0xffffffffu, part, 1);
            part += __shfl_xor_sync(0xffffffffu, part, 2);
            if ((tid & 3) == 0) rss[r] = part;
        }
        cp_async_wait_all();
        __syncthreads();

        // ---- fp16 GEMM screen, 16-col chunks; fold (best,second) per row-slot ----
        unsigned long long bk1[4], bk2[4];
        #pragma unroll
        for (int i = 0; i < 4; ++i) { bk1[i] = ~0ull; bk2[i] = ~0ull; }

        #pragma unroll 1
        for (int ch = 0; ch < 4; ++ch) {
            const int n_base = n_base0 + ch * 16;
            const uint32_t bCh = bOff + (uint32_t)n_base * ROWB;
            float acc[2][2][4];
            #pragma unroll
            for (int mt = 0; mt < 2; ++mt)
                #pragma unroll
                for (int nt = 0; nt < 2; ++nt)
                    #pragma unroll
                    for (int c = 0; c < 4; ++c) acc[mt][nt][c] = 0.f;

            #pragma unroll 4
            for (int ks = 0; ks < 8; ++ks) {
                const uint32_t k2 = (uint32_t)ks * 32;
                uint32_t a0[4], a1[4], b[4];
                ldm_x4(a0[0], a0[1], a0[2], a0[3], rbT + aOff + k2);
                ldm_x4(a1[0], a1[1], a1[2], a1[3], rbT + aOff + k2 + 16 * ROWB);
                ldm_x4(b[0],  b[1],  b[2],  b[3],  cbS + bCh + k2);
                mma_f16(acc[0][0][0], acc[0][0][1], acc[0][0][2], acc[0][0][3],
                        a0[0], a0[1], a0[2], a0[3], b[0], b[1]);
                mma_f16(acc[0][1][0], acc[0][1][1], acc[0][1][2], acc[0][1][3],
                        a0[0], a0[1], a0[2], a0[3], b[2], b[3]);
                mma_f16(acc[1][0][0], acc[1][0][1], acc[1][0][2], acc[1][0][3],
                        a1[0], a1[1], a1[2], a1[3], b[0], b[1]);
                mma_f16(acc[1][1][0], acc[1][1][1], acc[1][1][2], acc[1][1][3],
                        a1[0], a1[1], a1[2], a1[3], b[2], b[3]);
            }
            #pragma unroll
            for (int mt = 0; mt < 2; ++mt)
                #pragma unroll
                for (int h = 0; h < 2; ++h) {
                    int row = m_base + mt * 16 + h * 8 + qr;
                    float rv = rss[row];
                    int sl = mt * 2 + h;
                    #pragma unroll
                    for (int nt = 0; nt < 2; ++nt)
                        #pragma unroll
                        for (int p = 0; p < 2; ++p) {
                            int k = n_base + nt * 8 + qc + p;
                            float d2 = __fadd_rn(
                                __fadd_rn(rv, __fmul_rn(-2.f, acc[mt][nt][h * 2 + p])),
                                csq[k]);
                            upd2(bk1[sl], bk2[sl],
                                 ((unsigned long long)ford(d2) << 32) | (unsigned)k);
                        }
                }
        }
        #pragma unroll
        for (int i = 0; i < 4; ++i) {
            unsigned long long b1 = bk1[i], b2 = bk2[i];
            mrg2(b1, b2, __shfl_xor_sync(0xffffffffu, b1, 1),
                         __shfl_xor_sync(0xffffffffu, b2, 1));
            mrg2(b1, b2, __shfl_xor_sync(0xffffffffu, b1, 2),
                         __shfl_xor_sync(0xffffffffu, b2, 2));
            int row = m_base + (i >> 1) * 16 + (i & 1) * 8 + qr;
            if ((lane & 3) == 0) { min1[row * 4 + wc] = b1; min2[row * 4 + wc] = b2; }
        }
        __syncthreads();

        if (tid < BM) {
            unsigned long long b1 = min1[tid * 4], b2 = min2[tid * 4];
            mrg2(b1, b2, min1[tid * 4 + 1], min2[tid * 4 + 1]);
            mrg2(b1, b2, min1[tid * 4 + 2], min2[tid * 4 + 2]);
            mrg2(b1, b2, min1[tid * 4 + 3], min2[tid * 4 + 3]);
            float amin = unford((uint32_t)(b1 >> 32));
            float d2nd = unford((uint32_t)(b2 >> 32));
            // margin = rigorous fp16 screen bound + absolute slop (validated rel_err=0.0)
            float cutv = amin + (1.0f / 512.0f) * sqrtf(rss[tid]) * g_cmax[stage] + 1e-3f;
            bestk[tid] = b1;
            need[tid]  = (d2nd <= cutv) ? 1 : 0;
        }
        __syncthreads();

        // ---- rescue: exact full 256-scan via TRANSPOSED codebook (coalesced) ----
        const float* ctT = g_cbT + (size_t)stage * DD * KK;
        #pragma unroll 1
        for (int rr = 0; rr < 8; ++rr) {
            int lrow = wid * 8 + rr;
            if (!need[lrow]) continue;                   // warp-uniform
            int n = rowBase + lrow;
            const float4* xr = (const float4*)(x + (size_t)n * DD);
            const float4* pr = (const float4*)(rec + lrow * DD);
            float rv = rss[lrow];
            const int kbase = lane * 8;
            float a[8];
            #pragma unroll
            for (int j = 0; j < 8; ++j) a[j] = 0.f;
            #pragma unroll 2
            for (int c2 = 0; c2 < 32; ++c2) {
                float4 xv = __ldg(xr + c2);
                float4 pv = pr[c2];
                float rd[4];
                rd[0] = xv.x - pv.x; rd[1] = xv.y - pv.y;
                rd[2] = xv.z - pv.z; rd[3] = xv.w - pv.w;
                #pragma unroll
                for (int q = 0; q < 4; ++q) {
                    const int d = c2 * 4 + q;
                    const float4* crow = (const float4*)(ctT + (size_t)d * KK + kbase);
                    float4 c0 = __ldg(crow);
                    float4 c1 = __ldg(crow + 1);
                    a[0] = fmaf(rd[q], c0.x, a[0]);
                    a[1] = fmaf(rd[q], c0.y, a[1]);
                    a[2] = fmaf(rd[q], c0.z, a[2]);
                    a[3] = fmaf(rd[q], c0.w, a[3]);
                    a[4] = fmaf(rd[q], c1.x, a[4]);
                    a[5] = fmaf(rd[q], c1.y, a[5]);
                    a[6] = fmaf(rd[q], c1.z, a[6]);
                    a[7] = fmaf(rd[q], c1.w, a[7]);
                }
            }
            unsigned long long bw = ~0ull;
            #pragma unroll
            for (int j = 0; j < 8; ++j) {
                int k = kbase + j;
                float d2e = __fadd_rn(__fadd_rn(rv, __fmul_rn(-2.0f, a[j])), csq[k]);
                unsigned long long pk =
                    ((unsigned long long)ford(d2e) << 32) | (unsigned)k;
                if (pk < bw) bw = pk;
            }
            #pragma unroll
            for (int off = 16; off > 0; off >>= 1) {
                unsigned long long o = __shfl_xor_sync(0xffffffffu, bw, off);
                if (o < bw) bw = o;
            }
            if (lane == 0) bestk[lrow] = bw;
        }
        __syncwarp();

        // ---- outputs: full one-hot row (stcs) + recon update + side (stcs) ----
        #pragma unroll 1
        for (int rr = 0; rr < 8; ++rr) {
            int lrow = wid * 8 + rr;
            int n    = rowBase + lrow;
            int bidx = (int)(bestk[lrow] & 0xffffffffull);

            float4* crow = (float4*)(codes + (size_t)n * (MM * KK) + (size_t)stage * KK);
            #pragma unroll
            for (int t = 0; t < 2; ++t) {
                int j  = lane + 32 * t;
                int k0 = j * 4;
                float4 v;
                v.x = (k0     == bidx) ? 1.0f : 0.0f;
                v.y = (k0 + 1 == bidx) ? 1.0f : 0.0f;
                v.z = (k0 + 2 == bidx) ? 1.0f : 0.0f;
                v.w = (k0 + 3 == bidx) ? 1.0f : 0.0f;
                __stcs(crow + j, v);
            }

            float4 cv = __ldg((const float4*)(C + (size_t)bidx * DD) + lane);
            float4 pp = ((const float4*)(rec + lrow * DD))[lane];
            float4 v;
            v.x = __fadd_rn(pp.x, cv.x);
            v.y = __fadd_rn(pp.y, cv.y);
            v.z = __fadd_rn(pp.z, cv.z);
            v.w = __fadd_rn(pp.w, cv.w);
            ((float4*)(rec + lrow * DD))[lane] = v;
            __stcs((float4*)(side + ((size_t)stage * NN + n) * DD) + lane, v);
            if (last) __stcs((float4*)(xrecon + (size_t)n * DD) + lane, v);
        }
        __syncthreads();   // recon/RB/CB reuse next stage
    }
}

extern "C" void kernel_launch(void* const* d_in, const int* in_sizes, int n_in,
                              void* d_out, int out_size)
{
    (void)in_sizes; (void)n_in; (void)out_size;
    const float* x  = (const float*)d_in[0];            // (N, D)
    const float* cb = (const float*)d_in[1];            // (M, K, D)

    float* out    = (float*)d_out;
    float* xrecon = out;                                // (N, D)
    float* codes  = out + (size_t)NN * DD;              // (N, M, K)
    float* side   = codes + (size_t)NN * MM * KK;       // (M, N, D)

    cudaFuncSetAttribute(rq_fused_kernel,
                         cudaFuncAttributeMaxDynamicSharedMemorySize, SM_BYTES);

    csq_prep_kernel<<<MM, KK>>>(cb);
    cbt_prep_kernel<<<dim3(MM, DD), KK>>>(cb);
    cbh_prep_kernel<<<MM, KK>>>(cb);

    rq_fused_kernel<<<NN / BM, THREADS, SM_BYTES>>>(x, cb, codes, side, xrecon);
}

// round 15
// speedup vs baseline: 1.1946x; 1.1946x over previous
#include <cuda_runtime.h>
#include <cuda_fp16.h>
#include <cstdint>
#include <cfloat>

// Problem constants
#define NN 65536
#define DD 128
#define MM 8
#define KK 256

#define BM      128
#define THREADS 512            // 16 warps: wr = wid&3 (32-row group), wc = wid>>2 (64-col strip)

// fp16 tile row stride: 136 elems = 272B; 272 % 128 = 16 -> ldmatrix conflict-free
#define ROWB 272

// smem layout (byte offsets)
#define SM_CB    0                       // 256*272 = 69632
#define SM_RB    69632                   // 128*272 = 34816
#define SM_REC   104448                  // recon fp32: 128*128*4 = 65536
#define SM_CSQ   169984                  // 1024
#define SM_RSS   171008                  // 512
#define SM_MIN1  171520                  // u64 keys: 128*4*8 = 4096
#define SM_MIN2  175616                  // float seconds: 128*4*4 = 2048
#define SM_BESTK 177664                  // 128*8 = 1024
#define SM_NEED  178688                  // 128*4 = 512
#define SM_BYTES 179200                  // 175 KB -> 1 CTA/SM

__device__ float g_csq[MM][KK];
__device__ float g_cmax[MM];
// transposed fp32 codebooks: g_cbT[st][d][k] (1MB, L2-resident) -> coalesced rescue
__device__ float g_cbT[(size_t)MM * DD * KK];
// fp16 codebook pre-packed in the exact padded smem image -> cp.async straight in
__device__ __align__(16) char g_cbH[MM][(size_t)KK * ROWB];

__device__ __forceinline__ uint32_t ford(float f) {
    uint32_t u = __float_as_uint(f);
    return (u & 0x80000000u) ? ~u : (u | 0x80000000u);
}
__device__ __forceinline__ float unford(uint32_t e) {
    return __uint_as_float((e & 0x80000000u) ? (e & 0x7fffffffu) : ~e);
}
__device__ __forceinline__ uint32_t smem_u32(const void* p) {
    uint32_t a;
    asm("{ .reg .u64 t; cvta.to.shared.u64 t, %1; cvt.u32.u64 %0, t; }" : "=r"(a) : "l"(p));
    return a;
}
__device__ __forceinline__ void cp_async16(uint32_t dst, const void* src) {
    asm volatile("cp.async.ca.shared.global [%0], [%1], 16;" :: "r"(dst), "l"(src));
}
__device__ __forceinline__ void cp_async_wait_all() {
    asm volatile("cp.async.commit_group;\n\tcp.async.wait_group 0;" ::: "memory");
}
__device__ __forceinline__ void ldm_x4(uint32_t& r0, uint32_t& r1, uint32_t& r2,
                                       uint32_t& r3, uint32_t addr) {
    asm volatile("ldmatrix.sync.aligned.m8n8.x4.shared.b16 {%0,%1,%2,%3}, [%4];"
                 : "=r"(r0), "=r"(r1), "=r"(r2), "=r"(r3) : "r"(addr));
}
__device__ __forceinline__ void mma_f16(float& c0, float& c1, float& c2, float& c3,
                                        uint32_t a0, uint32_t a1, uint32_t a2, uint32_t a3,
                                        uint32_t b0, uint32_t b1) {
    asm volatile("mma.sync.aligned.m16n8k16.row.col.f32.f16.f16.f32 "
                 "{%0,%1,%2,%3}, {%4,%5,%6,%7}, {%8,%9}, {%0,%1,%2,%3};"
                 : "+f"(c0), "+f"(c1), "+f"(c2), "+f"(c3)
                 : "r"(a0), "r"(a1), "r"(a2), "r"(a3), "r"(b0), "r"(b1));
}
// merge (key1,b1,b2) with another (ok,ob1,ob2): best key (lowest-k tie), b2 = 2nd value
__device__ __forceinline__ void mrgf(unsigned long long& k1, float& b1, float& b2,
                                     unsigned long long ok, float ob1, float ob2) {
    b2 = fminf(fminf(b2, ob2), fmaxf(b1, ob1));
    b1 = fminf(b1, ob1);
    if (ok < k1) k1 = ok;
}

__global__ void csq_prep_kernel(const float* __restrict__ cb) {
    int st = blockIdx.x;
    int k  = threadIdx.x;                  // 256 threads
    const float* row = cb + ((size_t)st * KK + k) * DD;
    float s = 0.f;
    for (int d = 0; d < DD; ++d) { float v = row[d]; s = fmaf(v, v, s); }
    g_csq[st][k] = s;
    __shared__ float red[KK];
    red[k] = s;
    __syncthreads();
    for (int off = 128; off > 0; off >>= 1) {
        if (k < off) red[k] = fmaxf(red[k], red[k + off]);
        __syncthreads();
    }
    if (k == 0) g_cmax[st] = sqrtf(red[0]);
}

// one-shot transpose: g_cbT[st][d][k] = cb[st][k][d]
__global__ void cbt_prep_kernel(const float* __restrict__ cb) {
    int st = blockIdx.x, d = blockIdx.y;
    int k  = threadIdx.x;                  // 256 threads
    g_cbT[((size_t)st * DD + d) * KK + k] = cb[((size_t)st * KK + k) * DD + d];
}

// one-shot fp16 pack in padded smem image (row k at byte k*ROWB, padding zeroed)
__global__ void cbh_prep_kernel(const float* __restrict__ cb) {
    int st = blockIdx.x;
    int k  = threadIdx.x;                  // 256 threads, one codeword row each
    const float* row = cb + ((size_t)st * KK + k) * DD;
    char* dst = g_cbH[st] + (size_t)k * ROWB;
    for (int dp = 0; dp < 64; ++dp) {
        float2 v = *(const float2*)(row + dp * 2);
        __half2 h = __floats2half2_rn(v.x, v.y);
        *(uint32_t*)(dst + dp * 4) = *(uint32_t*)&h;
    }
    for (int j = 0; j < 4; ++j) *(uint32_t*)(dst + 256 + j * 4) = 0u;  // padding
}

// ---- fused: all 8 stages in one kernel; recon tile lives in smem ----
__global__ __launch_bounds__(THREADS, 1)
void rq_fused_kernel(const float* __restrict__ x,
                     const float* __restrict__ cb,      // (M, K, D) fp32
                     float* __restrict__ codes,
                     float* __restrict__ side,          // (M, N, D)
                     float* __restrict__ xrecon)
{
    extern __shared__ char smem[];
    const uint32_t sbase = smem_u32(smem);
    float* csq  = (float*)(smem + SM_CSQ);
    float* rss  = (float*)(smem + SM_RSS);
    float* rec  = (float*)(smem + SM_REC);               // recon[r][d], stride 128
    unsigned long long* min1  = (unsigned long long*)(smem + SM_MIN1);
    float* min2 = (float*)(smem + SM_MIN2);
    unsigned long long* bestk = (unsigned long long*)(smem + SM_BESTK);
    int* need = (int*)(smem + SM_NEED);

    const int tid  = threadIdx.x;
    const int wid  = tid >> 5;
    const int lane = tid & 31;
    const int rowBase = blockIdx.x * BM;

    // zero recon tile
    #pragma unroll 4
    for (int i = tid; i < BM * DD / 4; i += THREADS)
        ((float4*)rec)[i] = make_float4(0.f, 0.f, 0.f, 0.f);
    __syncthreads();

    const int wr = wid & 3;
    const int wc = wid >> 2;                // 0..3: 64-col strip
    const int m_base  = wr * 32;
    const int n_base0 = wc * 64;
    const int qr = lane >> 2;
    const int qc = (lane & 3) * 2;
    const uint32_t aOff = (uint32_t)(((lane & 7) + ((lane >> 3) & 1) * 8 + m_base) * ROWB
                                     + ((lane >> 4) & 1) * 16);
    const uint32_t bOff = (uint32_t)(((lane & 7) + ((lane >> 4) & 1) * 8) * ROWB
                                     + ((lane >> 3) & 1) * 16);
    const uint32_t rbT = sbase + SM_RB, cbS = sbase + SM_CB;

    #pragma unroll 1
    for (int stage = 0; stage < MM; ++stage) {
        const float* C   = cb + (size_t)stage * KK * DD;
        const int    last = (stage == MM - 1);

        // ---- codebook fp16 tile via cp.async (overlaps with residual prep) ----
        {
            const char* src = g_cbH[stage];
            #pragma unroll
            for (int j = 0; j < 9; ++j) {
                int c16 = tid + j * THREADS;        // 4352 chunks of 16B
                if (c16 < (KK * ROWB) / 16)
                    cp_async16(sbase + SM_CB + c16 * 16, src + (size_t)c16 * 16);
            }
        }
        if (tid < KK) csq[tid] = g_csq[stage][tid];

        // ---- residual = x - recon; store fp16(-2*res) (exact x2 scale) + exact rss ----
        {
            int r  = tid >> 2;
            int c0 = (tid & 3) * 32;
            const float* xrow = x + (size_t)(rowBase + r) * DD + c0;
            const float* rrow = rec + r * DD + c0;
            float part = 0.f;
            #pragma unroll 4
            for (int j = 0; j < 32; j += 4) {
                float4 xv = *(const float4*)(xrow + j);
                float4 pv = *(const float4*)(rrow + j);
                float r0 = xv.x - pv.x, r1 = xv.y - pv.y;
                float r2 = xv.z - pv.z, r3 = xv.w - pv.w;
                __half2 h0 = __floats2half2_rn(-2.f * r0, -2.f * r1);
                __half2 h1 = __floats2half2_rn(-2.f * r2, -2.f * r3);
                uint2 pk = make_uint2(*(uint32_t*)&h0, *(uint32_t*)&h1);
                *(uint2*)(smem + SM_RB + r * ROWB + (c0 + j) * 2) = pk;
                part = fmaf(r0, r0, part); part = fmaf(r1, r1, part);
                part = fmaf(r2, r2, part); part = fmaf(r3, r3, part);
            }
            part += __shfl_xor_sync(0xffffffffu, part, 1);
            part += __shfl_xor_sync(0xffffffffu, part, 2);
            if ((tid & 3) == 0) rss[r] = part;
        }
        cp_async_wait_all();
        __syncthreads();

        // ---- fp16 GEMM screen; acc = -2*dot exactly; fold s = acc + csq (rv cancels) ----
        float bs1[4], bs2[4];          // per row-slot: best / second s-values
        int   bi1[4];                  // best index
        #pragma unroll
        for (int i = 0; i < 4; ++i) { bs1[i] = FLT_MAX; bs2[i] = FLT_MAX; bi1[i] = 0; }

        #pragma unroll 1
        for (int ch = 0; ch < 4; ++ch) {
            const int n_base = n_base0 + ch * 16;
            const uint32_t bCh = bOff + (uint32_t)n_base * ROWB;
            float acc[2][2][4];
            #pragma unroll
            for (int mt = 0; mt < 2; ++mt)
                #pragma unroll
                for (int nt = 0; nt < 2; ++nt)
                    #pragma unroll
                    for (int c = 0; c < 4; ++c) acc[mt][nt][c] = 0.f;

            #pragma unroll 4
            for (int ks = 0; ks < 8; ++ks) {
                const uint32_t k2 = (uint32_t)ks * 32;
                uint32_t a0[4], a1[4], b[4];
                ldm_x4(a0[0], a0[1], a0[2], a0[3], rbT + aOff + k2);
                ldm_x4(a1[0], a1[1], a1[2], a1[3], rbT + aOff + k2 + 16 * ROWB);
                ldm_x4(b[0],  b[1],  b[2],  b[3],  cbS + bCh + k2);
                mma_f16(acc[0][0][0], acc[0][0][1], acc[0][0][2], acc[0][0][3],
                        a0[0], a0[1], a0[2], a0[3], b[0], b[1]);
                mma_f16(acc[0][1][0], acc[0][1][1], acc[0][1][2], acc[0][1][3],
                        a0[0], a0[1], a0[2], a0[3], b[2], b[3]);
                mma_f16(acc[1][0][0], acc[1][0][1], acc[1][0][2], acc[1][0][3],
                        a1[0], a1[1], a1[2], a1[3], b[0], b[1]);
                mma_f16(acc[1][1][0], acc[1][1][1], acc[1][1][2], acc[1][1][3],
                        a1[0], a1[1], a1[2], a1[3], b[2], b[3]);
            }
            #pragma unroll
            for (int nt = 0; nt < 2; ++nt) {
                const int kb = n_base + nt * 8 + qc;
                float2 cs = *(const float2*)(csq + kb);
                #pragma unroll
                for (int mt = 0; mt < 2; ++mt)
                    #pragma unroll
                    for (int h = 0; h < 2; ++h) {
                        const int sl = mt * 2 + h;
                        #pragma unroll
                        for (int p = 0; p < 2; ++p) {
                            float sA = __fadd_rn(acc[mt][nt][h * 2 + p],
                                                 p ? cs.y : cs.x);
                            if (sA < bs1[sl]) {
                                bs2[sl] = bs1[sl]; bs1[sl] = sA; bi1[sl] = kb + p;
                            } else {
                                bs2[sl] = fminf(bs2[sl], sA);
                            }
                        }
                    }
            }
        }
        // quad-reduce (key packed only here), publish per-(row, strip) best/second
        #pragma unroll
        for (int i = 0; i < 4; ++i) {
            unsigned long long k1 =
                ((unsigned long long)ford(bs1[i]) << 32) | (unsigned)bi1[i];
            float b1 = bs1[i], b2 = bs2[i];
            #pragma unroll
            for (int off = 1; off <= 2; off <<= 1) {
                unsigned long long ok = __shfl_xor_sync(0xffffffffu, k1, off);
                float ob1 = __shfl_xor_sync(0xffffffffu, b1, off);
                float ob2 = __shfl_xor_sync(0xffffffffu, b2, off);
                mrgf(k1, b1, b2, ok, ob1, ob2);
            }
            int row = m_base + (i >> 1) * 16 + (i & 1) * 8 + qr;
            if ((lane & 3) == 0) { min1[row * 4 + wc] = k1; min2[row * 4 + wc] = b2; }
        }
        __syncthreads();

        if (tid < BM) {
            unsigned long long k1 = min1[tid * 4];
            float b1 = unford((uint32_t)(k1 >> 32));
            float b2 = min2[tid * 4];
            #pragma unroll
            for (int s2 = 1; s2 < 4; ++s2) {
                unsigned long long ok = min1[tid * 4 + s2];
                mrgf(k1, b1, b2, ok, unford((uint32_t)(ok >> 32)), min2[tid * 4 + s2]);
            }
            // margin identical to validated config: (1/512)*sqrt(rss)*cmax + 1e-3
            float cutv = b1 + (1.0f / 512.0f) * sqrtf(rss[tid]) * g_cmax[stage] + 1e-3f;
            bestk[tid] = k1;
            need[tid]  = (b2 <= cutv) ? 1 : 0;
        }
        __syncthreads();

        // ---- rescue: exact full 256-scan via TRANSPOSED codebook (coalesced) ----
        const float* ctT = g_cbT + (size_t)stage * DD * KK;
        #pragma unroll 1
        for (int rr = 0; rr < 8; ++rr) {
            int lrow = wid * 8 + rr;
            if (!need[lrow]) continue;                   // warp-uniform
            int n = rowBase + lrow;
            const float4* xr = (const float4*)(x + (size_t)n * DD);
            const float4* pr = (const float4*)(rec + lrow * DD);
            float rv = rss[lrow];
            const int kbase = lane * 8;
            float a[8];
            #pragma unroll
            for (int j = 0; j < 8; ++j) a[j] = 0.f;
            #pragma unroll 4
            for (int c2 = 0; c2 < 32; ++c2) {
                float4 xv = __ldg(xr + c2);
                float4 pv = pr[c2];
                float rd[4];
                rd[0] = xv.x - pv.x; rd[1] = xv.y - pv.y;
                rd[2] = xv.z - pv.z; rd[3] = xv.w - pv.w;
                #pragma unroll
                for (int q = 0; q < 4; ++q) {
                    const int d = c2 * 4 + q;
                    const float4* crow = (const float4*)(ctT + (size_t)d * KK + kbase);
                    float4 c0 = __ldg(crow);
                    float4 c1 = __ldg(crow + 1);
                    a[0] = fmaf(rd[q], c0.x, a[0]);
                    a[1] = fmaf(rd[q], c0.y, a[1]);
                    a[2] = fmaf(rd[q], c0.z, a[2]);
                    a[3] = fmaf(rd[q], c0.w, a[3]);
                    a[4] = fmaf(rd[q], c1.x, a[4]);
                    a[5] = fmaf(rd[q], c1.y, a[5]);
                    a[6] = fmaf(rd[q], c1.z, a[6]);
                    a[7] = fmaf(rd[q], c1.w, a[7]);
                }
            }
            unsigned long long bw = ~0ull;
            #pragma unroll
            for (int j = 0; j < 8; ++j) {
                int k = kbase + j;
                float d2e = __fadd_rn(__fadd_rn(rv, __fmul_rn(-2.0f, a[j])), csq[k]);
                unsigned long long pk =
                    ((unsigned long long)ford(d2e) << 32) | (unsigned)k;
                if (pk < bw) bw = pk;
            }
            #pragma unroll
            for (int off = 16; off > 0; off >>= 1) {
                unsigned long long o = __shfl_xor_sync(0xffffffffu, bw, off);
                if (o < bw) bw = o;
            }
            if (lane == 0) bestk[lrow] = bw;
        }
        __syncwarp();

        // ---- outputs: one-hot (stcs) + recon update + side (stcs); batched LDGs ----
        #pragma unroll 1
        for (int g = 0; g < 2; ++g) {
            int bx[4];
            float4 cv[4];
            #pragma unroll
            for (int r4 = 0; r4 < 4; ++r4) {
                int lrow = wid * 8 + g * 4 + r4;
                bx[r4] = (int)(bestk[lrow] & 0xffffffffull);
                cv[r4] = __ldg((const float4*)(C + (size_t)bx[r4] * DD) + lane);
            }
            #pragma unroll
            for (int r4 = 0; r4 < 4; ++r4) {
                int lrow = wid * 8 + g * 4 + r4;
                int n    = rowBase + lrow;
                int bidx = bx[r4];

                float4* crow =
                    (float4*)(codes + (size_t)n * (MM * KK) + (size_t)stage * KK);
                #pragma unroll
                for (int t = 0; t < 2; ++t) {
                    int j  = lane + 32 * t;
                    int k0 = j * 4;
                    float4 v;
                    v.x = (k0     == bidx) ? 1.0f : 0.0f;
                    v.y = (k0 + 1 == bidx) ? 1.0f : 0.0f;
                    v.z = (k0 + 2 == bidx) ? 1.0f : 0.0f;
                    v.w = (k0 + 3 == bidx) ? 1.0f : 0.0f;
                    __stcs(crow + j, v);
                }

                float4 pp = ((const float4*)(rec + lrow * DD))[lane];
                float4 v;
                v.x = __fadd_rn(pp.x, cv[r4].x);
                v.y = __fadd_rn(pp.y, cv[r4].y);
                v.z = __fadd_rn(pp.z, cv[r4].z);
                v.w = __fadd_rn(pp.w, cv[r4].w);
                ((float4*)(rec + lrow * DD))[lane] = v;
                __stcs((float4*)(side + ((size_t)stage * NN + n) * DD) + lane, v);
                if (last) __stcs((float4*)(xrecon + (size_t)n * DD) + lane, v);
            }
        }
        __syncthreads();   // recon/RB/CB reuse next stage
    }
}

extern "C" void kernel_launch(void* const* d_in, const int* in_sizes, int n_in,
                              void* d_out, int out_size)
{
    (void)in_sizes; (void)n_in; (void)out_size;
    const float* x  = (const float*)d_in[0];            // (N, D)
    const float* cb = (const float*)d_in[1];            // (M, K, D)

    float* out    = (float*)d_out;
    float* xrecon = out;                                // (N, D)
    float* codes  = out + (size_t)NN * DD;              // (N, M, K)
    float* side   = codes + (size_t)NN * MM * KK;       // (M, N, D)

    cudaFuncSetAttribute(rq_fused_kernel,
                         cudaFuncAttributeMaxDynamicSharedMemorySize, SM_BYTES);

    csq_prep_kernel<<<MM, KK>>>(cb);
    cbt_prep_kernel<<<dim3(MM, DD), KK>>>(cb);
    cbh_prep_kernel<<<MM, KK>>>(cb);

    rq_fused_kernel<<<NN / BM, THREADS, SM_BYTES>>>(x, cb, codes, side, xrecon);
}

// round 16
// speedup vs baseline: 1.2294x; 1.0291x over previous
#include <cuda_runtime.h>
#include <cuda_fp16.h>
#include <cstdint>
#include <cfloat>

// Problem constants
#define NN 65536
#define DD 128
#define MM 8
#define KK 256

#define BM      128
#define THREADS 512            // 16 warps: wr = wid&7 (16-row group), wc = wid>>3 (128-col strip)

// fp16 tile row stride: 136 elems = 272B; 272 % 128 = 16 -> ldmatrix conflict-free
#define ROWB 272

// smem layout (byte offsets)
#define SM_CB    0                       // 256*272 = 69632
#define SM_RB    69632                   // 128*272 = 34816
#define SM_REC   104448                  // recon fp32: 128*128*4 = 65536
#define SM_CSQ   169984                  // 1024
#define SM_RSS   171008                  // 512
#define SM_MIN1  171520                  // u64 keys: 128*2*8 = 2048
#define SM_MIN2  173568                  // float seconds: 128*2*4 = 1024
#define SM_BESTK 174592                  // 1024
#define SM_NEED  175616                  // 512
#define SM_BYTES 176128                  // 172 KB -> 1 CTA/SM

__device__ float g_csq[MM][KK];
__device__ float g_cmax[MM];
// transposed fp32 codebooks: g_cbT[st][d][k] (1MB, L2-resident) -> coalesced rescue
__device__ float g_cbT[(size_t)MM * DD * KK];
// fp16 codebook pre-packed in the exact padded smem image -> cp.async straight in
__device__ __align__(16) char g_cbH[MM][(size_t)KK * ROWB];

__device__ __forceinline__ uint32_t ford(float f) {
    uint32_t u = __float_as_uint(f);
    return (u & 0x80000000u) ? ~u : (u | 0x80000000u);
}
__device__ __forceinline__ float unford(uint32_t e) {
    return __uint_as_float((e & 0x80000000u) ? (e & 0x7fffffffu) : ~e);
}
__device__ __forceinline__ uint32_t smem_u32(const void* p) {
    uint32_t a;
    asm("{ .reg .u64 t; cvta.to.shared.u64 t, %1; cvt.u32.u64 %0, t; }" : "=r"(a) : "l"(p));
    return a;
}
__device__ __forceinline__ void cp_async16(uint32_t dst, const void* src) {
    asm volatile("cp.async.ca.shared.global [%0], [%1], 16;" :: "r"(dst), "l"(src));
}
__device__ __forceinline__ void cp_async_wait_all() {
    asm volatile("cp.async.commit_group;\n\tcp.async.wait_group 0;" ::: "memory");
}
__device__ __forceinline__ void ldm_x4(uint32_t& r0, uint32_t& r1, uint32_t& r2,
                                       uint32_t& r3, uint32_t addr) {
    asm volatile("ldmatrix.sync.aligned.m8n8.x4.shared.b16 {%0,%1,%2,%3}, [%4];"
                 : "=r"(r0), "=r"(r1), "=r"(r2), "=r"(r3) : "r"(addr));
}
__device__ __forceinline__ void mma_f16(float& c0, float& c1, float& c2, float& c3,
                                        uint32_t a0, uint32_t a1, uint32_t a2, uint32_t a3,
                                        uint32_t b0, uint32_t b1) {
    asm volatile("mma.sync.aligned.m16n8k16.row.col.f32.f16.f16.f32 "
                 "{%0,%1,%2,%3}, {%4,%5,%6,%7}, {%8,%9}, {%0,%1,%2,%3};"
                 : "+f"(c0), "+f"(c1), "+f"(c2), "+f"(c3)
                 : "r"(a0), "r"(a1), "r"(a2), "r"(a3), "r"(b0), "r"(b1));
}
// merge (key1,b1,b2) with another (ok,ob1,ob2): best key (lowest-k tie), b2 = 2nd value
__device__ __forceinline__ void mrgf(unsigned long long& k1, float& b1, float& b2,
                                     unsigned long long ok, float ob1, float ob2) {
    b2 = fminf(fminf(b2, ob2), fmaxf(b1, ob1));
    b1 = fminf(b1, ob1);
    if (ok < k1) k1 = ok;
}

__global__ void csq_prep_kernel(const float* __restrict__ cb) {
    int st = blockIdx.x;
    int k  = threadIdx.x;                  // 256 threads
    const float* row = cb + ((size_t)st * KK + k) * DD;
    float s = 0.f;
    for (int d = 0; d < DD; ++d) { float v = row[d]; s = fmaf(v, v, s); }
    g_csq[st][k] = s;
    __shared__ float red[KK];
    red[k] = s;
    __syncthreads();
    for (int off = 128; off > 0; off >>= 1) {
        if (k < off) red[k] = fmaxf(red[k], red[k + off]);
        __syncthreads();
    }
    if (k == 0) g_cmax[st] = sqrtf(red[0]);
}

// one-shot transpose: g_cbT[st][d][k] = cb[st][k][d]
__global__ void cbt_prep_kernel(const float* __restrict__ cb) {
    int st = blockIdx.x, d = blockIdx.y;
    int k  = threadIdx.x;                  // 256 threads
    g_cbT[((size_t)st * DD + d) * KK + k] = cb[((size_t)st * KK + k) * DD + d];
}

// one-shot fp16 pack in padded smem image (row k at byte k*ROWB, padding zeroed)
__global__ void cbh_prep_kernel(const float* __restrict__ cb) {
    int st = blockIdx.x;
    int k  = threadIdx.x;                  // 256 threads, one codeword row each
    const float* row = cb + ((size_t)st * KK + k) * DD;
    char* dst = g_cbH[st] + (size_t)k * ROWB;
    for (int dp = 0; dp < 64; ++dp) {
        float2 v = *(const float2*)(row + dp * 2);
        __half2 h = __floats2half2_rn(v.x, v.y);
        *(uint32_t*)(dst + dp * 4) = *(uint32_t*)&h;
    }
    for (int j = 0; j < 4; ++j) *(uint32_t*)(dst + 256 + j * 4) = 0u;  // padding
}

// ---- fused: all 8 stages in one kernel; recon tile lives in smem ----
__global__ __launch_bounds__(THREADS, 1)
void rq_fused_kernel(const float* __restrict__ x,
                     const float* __restrict__ cb,      // (M, K, D) fp32
                     float* __restrict__ codes,
                     float* __restrict__ side,          // (M, N, D)
                     float* __restrict__ xrecon)
{
    extern __shared__ char smem[];
    const uint32_t sbase = smem_u32(smem);
    float* csq  = (float*)(smem + SM_CSQ);
    float* rss  = (float*)(smem + SM_RSS);
    float* rec  = (float*)(smem + SM_REC);               // recon[r][d], stride 128
    unsigned long long* min1  = (unsigned long long*)(smem + SM_MIN1);
    float* min2 = (float*)(smem + SM_MIN2);
    unsigned long long* bestk = (unsigned long long*)(smem + SM_BESTK);
    int* need = (int*)(smem + SM_NEED);

    const int tid  = threadIdx.x;
    const int wid  = tid >> 5;
    const int lane = tid & 31;
    const int rowBase = blockIdx.x * BM;

    // zero recon tile
    #pragma unroll 4
    for (int i = tid; i < BM * DD / 4; i += THREADS)
        ((float4*)rec)[i] = make_float4(0.f, 0.f, 0.f, 0.f);
    __syncthreads();

    const int wr = wid & 7;                 // 8 row groups of 16
    const int wc = wid >> 3;                // 2 col strips of 128
    const int m_base  = wr * 16;
    const int n_base0 = wc * 128;
    const int qr = lane >> 2;
    const int qc = (lane & 3) * 2;
    const uint32_t aOff = (uint32_t)(((lane & 7) + ((lane >> 3) & 1) * 8 + m_base) * ROWB
                                     + ((lane >> 4) & 1) * 16);
    const uint32_t bOff = (uint32_t)(((lane & 7) + ((lane >> 4) & 1) * 8) * ROWB
                                     + ((lane >> 3) & 1) * 16);
    const uint32_t rbT = sbase + SM_RB, cbS = sbase + SM_CB;

    #pragma unroll 1
    for (int stage = 0; stage < MM; ++stage) {
        const float* C   = cb + (size_t)stage * KK * DD;
        const int    last = (stage == MM - 1);

        // ---- codebook fp16 tile via cp.async (overlaps with residual prep) ----
        {
            const char* src = g_cbH[stage];
            #pragma unroll
            for (int j = 0; j < 9; ++j) {
                int c16 = tid + j * THREADS;        // 4352 chunks of 16B
                if (c16 < (KK * ROWB) / 16)
                    cp_async16(sbase + SM_CB + c16 * 16, src + (size_t)c16 * 16);
            }
        }
        if (tid < KK) csq[tid] = g_csq[stage][tid];

        // ---- residual = x - recon; store fp16(-2*res) (exact x2 scale) + exact rss ----
        {
            int r  = tid >> 2;
            int c0 = (tid & 3) * 32;
            const float* xrow = x + (size_t)(rowBase + r) * DD + c0;
            const float* rrow = rec + r * DD + c0;
            float part = 0.f;
            #pragma unroll 4
            for (int j = 0; j < 32; j += 4) {
                float4 xv = *(const float4*)(xrow + j);
                float4 pv = *(const float4*)(rrow + j);
                float r0 = xv.x - pv.x, r1 = xv.y - pv.y;
                float r2 = xv.z - pv.z, r3 = xv.w - pv.w;
                __half2 h0 = __floats2half2_rn(-2.f * r0, -2.f * r1);
                __half2 h1 = __floats2half2_rn(-2.f * r2, -2.f * r3);
                uint2 pk = make_uint2(*(uint32_t*)&h0, *(uint32_t*)&h1);
                *(uint2*)(smem + SM_RB + r * ROWB + (c0 + j) * 2) = pk;
                part = fmaf(r0, r0, part); part = fmaf(r1, r1, part);
                part = fmaf(r2, r2, part); part = fmaf(r3, r3, part);
            }
            part += __shfl_xor_sync(0xffffffffu, part, 1);
            part += __shfl_xor_sync(0xffffffffu, part, 2);
            if ((tid & 3) == 0) rss[r] = part;
        }
        cp_async_wait_all();
        __syncthreads();

        // ---- A fragments hoisted: one m16k16 ldmatrix per ks, held across all chunks ----
        uint32_t a[8][4];
        #pragma unroll
        for (int ks = 0; ks < 8; ++ks)
            ldm_x4(a[ks][0], a[ks][1], a[ks][2], a[ks][3],
                   rbT + aOff + (uint32_t)ks * 32);

        // ---- fp16 GEMM screen: 8 chunks of 16 cols; fold s = acc + csq (rv cancels) ----
        float bs1[2], bs2[2];          // per row-slot (h): best / second s-values
        int   bi1[2];
        #pragma unroll
        for (int i = 0; i < 2; ++i) { bs1[i] = FLT_MAX; bs2[i] = FLT_MAX; bi1[i] = 0; }

        #pragma unroll 1
        for (int ch = 0; ch < 8; ++ch) {
            const int n_base = n_base0 + ch * 16;
            const uint32_t bCh = bOff + (uint32_t)n_base * ROWB;
            float acc[2][4];
            #pragma unroll
            for (int nt = 0; nt < 2; ++nt)
                #pragma unroll
                for (int c = 0; c < 4; ++c) acc[nt][c] = 0.f;

            #pragma unroll
            for (int ks = 0; ks < 8; ++ks) {
                uint32_t b[4];
                ldm_x4(b[0], b[1], b[2], b[3], cbS + bCh + (uint32_t)ks * 32);
                mma_f16(acc[0][0], acc[0][1], acc[0][2], acc[0][3],
                        a[ks][0], a[ks][1], a[ks][2], a[ks][3], b[0], b[1]);
                mma_f16(acc[1][0], acc[1][1], acc[1][2], acc[1][3],
                        a[ks][0], a[ks][1], a[ks][2], a[ks][3], b[2], b[3]);
            }
            #pragma unroll
            for (int nt = 0; nt < 2; ++nt) {
                const int kb = n_base + nt * 8 + qc;
                float2 cs = *(const float2*)(csq + kb);
                #pragma unroll
                for (int h = 0; h < 2; ++h) {
                    #pragma unroll
                    for (int p = 0; p < 2; ++p) {
                        float sA = __fadd_rn(acc[nt][h * 2 + p], p ? cs.y : cs.x);
                        if (sA < bs1[h]) {
                            bs2[h] = bs1[h]; bs1[h] = sA; bi1[h] = kb + p;
                        } else {
                            bs2[h] = fminf(bs2[h], sA);
                        }
                    }
                }
            }
        }
        // quad-reduce (key packed only here), publish per-(row, strip) best/second
        #pragma unroll
        for (int i = 0; i < 2; ++i) {
            unsigned long long k1 =
                ((unsigned long long)ford(bs1[i]) << 32) | (unsigned)bi1[i];
            float b1 = bs1[i], b2 = bs2[i];
            #pragma unroll
            for (int off = 1; off <= 2; off <<= 1) {
                unsigned long long ok = __shfl_xor_sync(0xffffffffu, k1, off);
                float ob1 = __shfl_xor_sync(0xffffffffu, b1, off);
                float ob2 = __shfl_xor_sync(0xffffffffu, b2, off);
                mrgf(k1, b1, b2, ok, ob1, ob2);
            }
            int row = m_base + i * 8 + qr;
            if ((lane & 3) == 0) { min1[row * 2 + wc] = k1; min2[row * 2 + wc] = b2; }
        }
        __syncthreads();

        if (tid < BM) {
            unsigned long long k1 = min1[tid * 2];
            float b1 = unford((uint32_t)(k1 >> 32));
            float b2 = min2[tid * 2];
            {
                unsigned long long ok = min1[tid * 2 + 1];
                mrgf(k1, b1, b2, ok, unford((uint32_t)(ok >> 32)), min2[tid * 2 + 1]);
            }
            // margin identical to validated config: (1/512)*sqrt(rss)*cmax + 1e-3
            float cutv = b1 + (1.0f / 512.0f) * sqrtf(rss[tid]) * g_cmax[stage] + 1e-3f;
            bestk[tid] = k1;
            need[tid]  = (b2 <= cutv) ? 1 : 0;
        }
        __syncthreads();

        // ---- rescue: exact full 256-scan via TRANSPOSED codebook (coalesced) ----
        const float* ctT = g_cbT + (size_t)stage * DD * KK;
        #pragma unroll 1
        for (int rr = 0; rr < 8; ++rr) {
            int lrow = wid * 8 + rr;
            if (!need[lrow]) continue;                   // warp-uniform
            int n = rowBase + lrow;
            const float4* xr = (const float4*)(x + (size_t)n * DD);
            const float4* pr = (const float4*)(rec + lrow * DD);
            float rv = rss[lrow];
            const int kbase = lane * 8;
            float aa[8];
            #pragma unroll
            for (int j = 0; j < 8; ++j) aa[j] = 0.f;
            #pragma unroll 4
            for (int c2 = 0; c2 < 32; ++c2) {
                float4 xv = __ldg(xr + c2);
                float4 pv = pr[c2];
                float rd[4];
                rd[0] = xv.x - pv.x; rd[1] = xv.y - pv.y;
                rd[2] = xv.z - pv.z; rd[3] = xv.w - pv.w;
                #pragma unroll
                for (int q = 0; q < 4; ++q) {
                    const int d = c2 * 4 + q;
                    const float4* crow = (const float4*)(ctT + (size_t)d * KK + kbase);
                    float4 c0 = __ldg(crow);
                    float4 c1 = __ldg(crow + 1);
                    aa[0] = fmaf(rd[q], c0.x, aa[0]);
                    aa[1] = fmaf(rd[q], c0.y, aa[1]);
                    aa[2] = fmaf(rd[q], c0.z, aa[2]);
                    aa[3] = fmaf(rd[q], c0.w, aa[3]);
                    aa[4] = fmaf(rd[q], c1.x, aa[4]);
                    aa[5] = fmaf(rd[q], c1.y, aa[5]);
                    aa[6] = fmaf(rd[q], c1.z, aa[6]);
                    aa[7] = fmaf(rd[q], c1.w, aa[7]);
                }
            }
            unsigned long long bw = ~0ull;
            #pragma unroll
            for (int j = 0; j < 8; ++j) {
                int k = kbase + j;
                float d2e = __fadd_rn(__fadd_rn(rv, __fmul_rn(-2.0f, aa[j])), csq[k]);
                unsigned long long pk =
                    ((unsigned long long)ford(d2e) << 32) | (unsigned)k;
                if (pk < bw) bw = pk;
            }
            #pragma unroll
            for (int off = 16; off > 0; off >>= 1) {
                unsigned long long o = __shfl_xor_sync(0xffffffffu, bw, off);
                if (o < bw) bw = o;
            }
            if (lane == 0) bestk[lrow] = bw;
        }
        __syncwarp();

        // ---- outputs: one-hot (zero stcs + poke) + recon update + side; batched LDGs ----
        #pragma unroll 1
        for (int g = 0; g < 2; ++g) {
            int bx[4];
            float4 cv[4];
            #pragma unroll
            for (int r4 = 0; r4 < 4; ++r4) {
                int lrow = wid * 8 + g * 4 + r4;
                bx[r4] = (int)(bestk[lrow] & 0xffffffffull);
                cv[r4] = __ldg((const float4*)(C + (size_t)bx[r4] * DD) + lane);
            }
            const float4 z4 = make_float4(0.f, 0.f, 0.f, 0.f);
            #pragma unroll
            for (int r4 = 0; r4 < 4; ++r4) {
                int n = rowBase + wid * 8 + g * 4 + r4;
                float4* crow =
                    (float4*)(codes + (size_t)n * (MM * KK) + (size_t)stage * KK);
                __stcs(crow + lane, z4);
                __stcs(crow + lane + 32, z4);
            }
            __syncwarp();
            if (lane < 4) {
                int n = rowBase + wid * 8 + g * 4 + lane;
                codes[(size_t)n * (MM * KK) + (size_t)stage * KK + bx[lane]] = 1.0f;
            }
            #pragma unroll
            for (int r4 = 0; r4 < 4; ++r4) {
                int lrow = wid * 8 + g * 4 + r4;
                int n    = rowBase + lrow;
                float4 pp = ((const float4*)(rec + lrow * DD))[lane];
                float4 v;
                v.x = __fadd_rn(pp.x, cv[r4].x);
                v.y = __fadd_rn(pp.y, cv[r4].y);
                v.z = __fadd_rn(pp.z, cv[r4].z);
                v.w = __fadd_rn(pp.w, cv[r4].w);
                ((float4*)(rec + lrow * DD))[lane] = v;
                __stcs((float4*)(side + ((size_t)stage * NN + n) * DD) + lane, v);
                if (last) __stcs((float4*)(xrecon + (size_t)n * DD) + lane, v);
            }
        }
        __syncthreads();   // recon/RB/CB reuse next stage
    }
}

extern "C" void kernel_launch(void* const* d_in, const int* in_sizes, int n_in,
                              void* d_out, int out_size)
{
    (void)in_sizes; (void)n_in; (void)out_size;
    const float* x  = (const float*)d_in[0];            // (N, D)
    const float* cb = (const float*)d_in[1];            // (M, K, D)

    float* out    = (float*)d_out;
    float* xrecon = out;                                // (N, D)
    float* codes  = out + (size_t)NN * DD;              // (N, M, K)
    float* side   = codes + (size_t)NN * MM * KK;       // (M, N, D)

    cudaFuncSetAttribute(rq_fused_kernel,
                         cudaFuncAttributeMaxDynamicSharedMemorySize, SM_BYTES);

    csq_prep_kernel<<<MM, KK>>>(cb);
    cbt_prep_kernel<<<dim3(MM, DD), KK>>>(cb);
    cbh_prep_kernel<<<MM, KK>>>(cb);

    rq_fused_kernel<<<NN / BM, THREADS, SM_BYTES>>>(x, cb, codes, side, xrecon);
}

// round 17
// speedup vs baseline: 1.3648x; 1.1101x over previous
#include <cuda_runtime.h>
#include <cuda_fp16.h>
#include <cstdint>
#include <cfloat>

// Problem constants
#define NN 65536
#define DD 128
#define MM 8
#define KK 256

#define BM      64
#define THREADS 256            // 8 warps: wr = wid&3 (16-row group), wc = wid>>2 (128-col strip)

// fp16 tile row stride: 136 elems = 272B; 272 % 128 = 16 -> ldmatrix conflict-free
#define ROWB 272

// smem layout (byte offsets)
#define SM_CB    0                       // 256*272 = 69632
#define SM_RB    69632                   // 64*272 = 17408
#define SM_CSQ   87040                   // 1024
#define SM_RSS   88064                   // 256
#define SM_MIN1  88320                   // u64 keys: 64*2*8 = 1024
#define SM_MIN2  89344                   // float seconds: 64*2*4 = 512
#define SM_BESTK 89856                   // 64*8 = 512
#define SM_NEED  90368                   // 64*4 = 256
#define SM_BYTES 90624                   // 88.5 KB -> 2 CTAs/SM

__device__ float g_csq[MM][KK];
__device__ float g_cmax[MM];
// transposed fp32 codebooks: g_cbT[st][d][k] (1MB, L2-resident) -> coalesced rescue
__device__ float g_cbT[(size_t)MM * DD * KK];
// fp16 codebook pre-packed in the exact padded smem image -> cp.async straight in
__device__ __align__(16) char g_cbH[MM][(size_t)KK * ROWB];

__device__ __forceinline__ uint32_t ford(float f) {
    uint32_t u = __float_as_uint(f);
    return (u & 0x80000000u) ? ~u : (u | 0x80000000u);
}
__device__ __forceinline__ float unford(uint32_t e) {
    return __uint_as_float((e & 0x80000000u) ? (e & 0x7fffffffu) : ~e);
}
__device__ __forceinline__ uint32_t smem_u32(const void* p) {
    uint32_t a;
    asm("{ .reg .u64 t; cvta.to.shared.u64 t, %1; cvt.u32.u64 %0, t; }" : "=r"(a) : "l"(p));
    return a;
}
__device__ __forceinline__ void cp_async16(uint32_t dst, const void* src) {
    asm volatile("cp.async.ca.shared.global [%0], [%1], 16;" :: "r"(dst), "l"(src));
}
__device__ __forceinline__ void cp_async_wait_all() {
    asm volatile("cp.async.commit_group;\n\tcp.async.wait_group 0;" ::: "memory");
}
__device__ __forceinline__ void ldm_x4(uint32_t& r0, uint32_t& r1, uint32_t& r2,
                                       uint32_t& r3, uint32_t addr) {
    asm volatile("ldmatrix.sync.aligned.m8n8.x4.shared.b16 {%0,%1,%2,%3}, [%4];"
                 : "=r"(r0), "=r"(r1), "=r"(r2), "=r"(r3) : "r"(addr));
}
__device__ __forceinline__ void mma_f16(float& c0, float& c1, float& c2, float& c3,
                                        uint32_t a0, uint32_t a1, uint32_t a2, uint32_t a3,
                                        uint32_t b0, uint32_t b1) {
    asm volatile("mma.sync.aligned.m16n8k16.row.col.f32.f16.f16.f32 "
                 "{%0,%1,%2,%3}, {%4,%5,%6,%7}, {%8,%9}, {%0,%1,%2,%3};"
                 : "+f"(c0), "+f"(c1), "+f"(c2), "+f"(c3)
                 : "r"(a0), "r"(a1), "r"(a2), "r"(a3), "r"(b0), "r"(b1));
}
// merge (key1,b1,b2) with another (ok,ob1,ob2): best key (lowest-k tie), b2 = 2nd value
__device__ __forceinline__ void mrgf(unsigned long long& k1, float& b1, float& b2,
                                     unsigned long long ok, float ob1, float ob2) {
    b2 = fminf(fminf(b2, ob2), fmaxf(b1, ob1));
    b1 = fminf(b1, ob1);
    if (ok < k1) k1 = ok;
}

__global__ void csq_prep_kernel(const float* __restrict__ cb) {
    int st = blockIdx.x;
    int k  = threadIdx.x;                  // 256 threads
    const float* row = cb + ((size_t)st * KK + k) * DD;
    float s = 0.f;
    for (int d = 0; d < DD; ++d) { float v = row[d]; s = fmaf(v, v, s); }
    g_csq[st][k] = s;
    __shared__ float red[KK];
    red[k] = s;
    __syncthreads();
    for (int off = 128; off > 0; off >>= 1) {
        if (k < off) red[k] = fmaxf(red[k], red[k + off]);
        __syncthreads();
    }
    if (k == 0) g_cmax[st] = sqrtf(red[0]);
}

// one-shot transpose: g_cbT[st][d][k] = cb[st][k][d]
__global__ void cbt_prep_kernel(const float* __restrict__ cb) {
    int st = blockIdx.x, d = blockIdx.y;
    int k  = threadIdx.x;                  // 256 threads
    g_cbT[((size_t)st * DD + d) * KK + k] = cb[((size_t)st * KK + k) * DD + d];
}

// one-shot fp16 pack in padded smem image (row k at byte k*ROWB, padding zeroed)
__global__ void cbh_prep_kernel(const float* __restrict__ cb) {
    int st = blockIdx.x;
    int k  = threadIdx.x;                  // 256 threads, one codeword row each
    const float* row = cb + ((size_t)st * KK + k) * DD;
    char* dst = g_cbH[st] + (size_t)k * ROWB;
    for (int dp = 0; dp < 64; ++dp) {
        float2 v = *(const float2*)(row + dp * 2);
        __half2 h = __floats2half2_rn(v.x, v.y);
        *(uint32_t*)(dst + dp * 4) = *(uint32_t*)&h;
    }
    for (int j = 0; j < 4; ++j) *(uint32_t*)(dst + 256 + j * 4) = 0u;  // padding
}

// ---- fused: all 8 stages; recon carried through side[] (L2-hot), 2 CTAs/SM ----
__global__ __launch_bounds__(THREADS, 2)
void rq_fused_kernel(const float* __restrict__ x,
                     const float* __restrict__ cb,      // (M, K, D) fp32
                     float* __restrict__ codes,
                     float* __restrict__ side,          // (M, N, D)
                     float* __restrict__ xrecon)
{
    extern __shared__ char smem[];
    const uint32_t sbase = smem_u32(smem);
    float* csq  = (float*)(smem + SM_CSQ);
    float* rss  = (float*)(smem + SM_RSS);
    unsigned long long* min1  = (unsigned long long*)(smem + SM_MIN1);
    float* min2 = (float*)(smem + SM_MIN2);
    unsigned long long* bestk = (unsigned long long*)(smem + SM_BESTK);
    int* need = (int*)(smem + SM_NEED);

    const int tid  = threadIdx.x;
    const int wid  = tid >> 5;
    const int lane = tid & 31;
    const int rowBase = blockIdx.x * BM;

    const int wr = wid & 3;                 // 4 row groups of 16
    const int wc = wid >> 2;                // 2 col strips of 128
    const int m_base  = wr * 16;
    const int n_base0 = wc * 128;
    const int qr = lane >> 2;
    const int qc = (lane & 3) * 2;
    const uint32_t aOff = (uint32_t)(((lane & 7) + ((lane >> 3) & 1) * 8 + m_base) * ROWB
                                     + ((lane >> 4) & 1) * 16);
    const uint32_t bOff = (uint32_t)(((lane & 7) + ((lane >> 4) & 1) * 8) * ROWB
                                     + ((lane >> 3) & 1) * 16);
    const uint32_t rbT = sbase + SM_RB, cbS = sbase + SM_CB;

    #pragma unroll 1
    for (int stage = 0; stage < MM; ++stage) {
        const float* C    = cb + (size_t)stage * KK * DD;
        const float* prev = (stage == 0) ? nullptr
                                         : (side + (size_t)(stage - 1) * NN * DD);
        const int    last = (stage == MM - 1);

        // ---- codebook fp16 tile via cp.async (overlaps with residual prep) ----
        {
            const char* src = g_cbH[stage];
            #pragma unroll
            for (int j = 0; j < 17; ++j) {
                int c16 = tid + j * THREADS;        // 4352 chunks of 16B
                cp_async16(sbase + SM_CB + c16 * 16, src + (size_t)c16 * 16);
            }
        }
        if (tid < KK) csq[tid] = g_csq[stage][tid];

        // ---- residual = x - prev; store fp16(-2*res) (exact x2 scale) + exact rss ----
        {
            int r  = tid >> 2;
            int c0 = (tid & 3) * 32;
            const float* xrow = x + (size_t)(rowBase + r) * DD + c0;
            const float* prow = prev ? prev + (size_t)(rowBase + r) * DD + c0 : nullptr;
            float part = 0.f;
            #pragma unroll 4
            for (int j = 0; j < 32; j += 4) {
                float4 xv = *(const float4*)(xrow + j);
                float4 pv = prow ? *(const float4*)(prow + j)
                                 : make_float4(0.f, 0.f, 0.f, 0.f);
                float r0 = xv.x - pv.x, r1 = xv.y - pv.y;
                float r2 = xv.z - pv.z, r3 = xv.w - pv.w;
                __half2 h0 = __floats2half2_rn(-2.f * r0, -2.f * r1);
                __half2 h1 = __floats2half2_rn(-2.f * r2, -2.f * r3);
                uint2 pk = make_uint2(*(uint32_t*)&h0, *(uint32_t*)&h1);
                *(uint2*)(smem + SM_RB + r * ROWB + (c0 + j) * 2) = pk;
                part = fmaf(r0, r0, part); part = fmaf(r1, r1, part);
                part = fmaf(r2, r2, part); part = fmaf(r3, r3, part);
            }
            part += __shfl_xor_sync(0xffffffffu, part, 1);
            part += __shfl_xor_sync(0xffffffffu, part, 2);
            if ((tid & 3) == 0) rss[r] = part;
        }
        cp_async_wait_all();
        __syncthreads();

        // ---- A fragments hoisted: one m16k16 ldmatrix per ks, held across chunks ----
        uint32_t a[8][4];
        #pragma unroll
        for (int ks = 0; ks < 8; ++ks)
            ldm_x4(a[ks][0], a[ks][1], a[ks][2], a[ks][3],
                   rbT + aOff + (uint32_t)ks * 32);

        // ---- fp16 GEMM screen: 8 chunks of 16 cols; fold s = acc + csq (rv cancels) ----
        float bs1[2], bs2[2];          // per row-slot (h): best / second s-values
        int   bi1[2];
        #pragma unroll
        for (int i = 0; i < 2; ++i) { bs1[i] = FLT_MAX; bs2[i] = FLT_MAX; bi1[i] = 0; }

        #pragma unroll 1
        for (int ch = 0; ch < 8; ++ch) {
            const int n_base = n_base0 + ch * 16;
            const uint32_t bCh = bOff + (uint32_t)n_base * ROWB;
            float acc[2][4];
            #pragma unroll
            for (int nt = 0; nt < 2; ++nt)
                #pragma unroll
                for (int c = 0; c < 4; ++c) acc[nt][c] = 0.f;

            #pragma unroll
            for (int ks = 0; ks < 8; ++ks) {
                uint32_t b[4];
                ldm_x4(b[0], b[1], b[2], b[3], cbS + bCh + (uint32_t)ks * 32);
                mma_f16(acc[0][0], acc[0][1], acc[0][2], acc[0][3],
                        a[ks][0], a[ks][1], a[ks][2], a[ks][3], b[0], b[1]);
                mma_f16(acc[1][0], acc[1][1], acc[1][2], acc[1][3],
                        a[ks][0], a[ks][1], a[ks][2], a[ks][3], b[2], b[3]);
            }
            #pragma unroll
            for (int nt = 0; nt < 2; ++nt) {
                const int kb = n_base + nt * 8 + qc;
                float2 cs = *(const float2*)(csq + kb);
                #pragma unroll
                for (int h = 0; h < 2; ++h) {
                    #pragma unroll
                    for (int p = 0; p < 2; ++p) {
                        float sA = __fadd_rn(acc[nt][h * 2 + p], p ? cs.y : cs.x);
                        if (sA < bs1[h]) {
                            bs2[h] = bs1[h]; bs1[h] = sA; bi1[h] = kb + p;
                        } else {
                            bs2[h] = fminf(bs2[h], sA);
                        }
                    }
                }
            }
        }
        // quad-reduce (key packed only here), publish per-(row, strip) best/second
        #pragma unroll
        for (int i = 0; i < 2; ++i) {
            unsigned long long k1 =
                ((unsigned long long)ford(bs1[i]) << 32) | (unsigned)bi1[i];
            float b1 = bs1[i], b2 = bs2[i];
            #pragma unroll
            for (int off = 1; off <= 2; off <<= 1) {
                unsigned long long ok = __shfl_xor_sync(0xffffffffu, k1, off);
                float ob1 = __shfl_xor_sync(0xffffffffu, b1, off);
                float ob2 = __shfl_xor_sync(0xffffffffu, b2, off);
                mrgf(k1, b1, b2, ok, ob1, ob2);
            }
            int row = m_base + i * 8 + qr;
            if ((lane & 3) == 0) { min1[row * 2 + wc] = k1; min2[row * 2 + wc] = b2; }
        }
        __syncthreads();

        if (tid < BM) {
            unsigned long long k1 = min1[tid * 2];
            float b1 = unford((uint32_t)(k1 >> 32));
            float b2 = min2[tid * 2];
            {
                unsigned long long ok = min1[tid * 2 + 1];
                mrgf(k1, b1, b2, ok, unford((uint32_t)(ok >> 32)), min2[tid * 2 + 1]);
            }
            // margin identical to validated config: (1/512)*sqrt(rss)*cmax + 1e-3
            float cutv = b1 + (1.0f / 512.0f) * sqrtf(rss[tid]) * g_cmax[stage] + 1e-3f;
            bestk[tid] = k1;
            need[tid]  = (b2 <= cutv) ? 1 : 0;
        }
        __syncthreads();

        // ---- rescue: exact full 256-scan via TRANSPOSED codebook (coalesced) ----
        const float* ctT = g_cbT + (size_t)stage * DD * KK;
        #pragma unroll 1
        for (int rr = 0; rr < 8; ++rr) {
            int lrow = wid * 8 + rr;
            if (!need[lrow]) continue;                   // warp-uniform
            int n = rowBase + lrow;
            const float4* xr = (const float4*)(x + (size_t)n * DD);
            const float4* pr = prev ? (const float4*)(prev + (size_t)n * DD) : nullptr;
            float rv = rss[lrow];
            const int kbase = lane * 8;
            float aa[8];
            #pragma unroll
            for (int j = 0; j < 8; ++j) aa[j] = 0.f;
            #pragma unroll 4
            for (int c2 = 0; c2 < 32; ++c2) {
                float4 xv = __ldg(xr + c2);
                float4 pv = pr ? __ldg(pr + c2) : make_float4(0.f, 0.f, 0.f, 0.f);
                float rd[4];
                rd[0] = xv.x - pv.x; rd[1] = xv.y - pv.y;
                rd[2] = xv.z - pv.z; rd[3] = xv.w - pv.w;
                #pragma unroll
                for (int q = 0; q < 4; ++q) {
                    const int d = c2 * 4 + q;
                    const float4* crow = (const float4*)(ctT + (size_t)d * KK + kbase);
                    float4 c0 = __ldg(crow);
                    float4 c1 = __ldg(crow + 1);
                    aa[0] = fmaf(rd[q], c0.x, aa[0]);
                    aa[1] = fmaf(rd[q], c0.y, aa[1]);
                    aa[2] = fmaf(rd[q], c0.z, aa[2]);
                    aa[3] = fmaf(rd[q], c0.w, aa[3]);
                    aa[4] = fmaf(rd[q], c1.x, aa[4]);
                    aa[5] = fmaf(rd[q], c1.y, aa[5]);
                    aa[6] = fmaf(rd[q], c1.z, aa[6]);
                    aa[7] = fmaf(rd[q], c1.w, aa[7]);
                }
            }
            unsigned long long bw = ~0ull;
            #pragma unroll
            for (int j = 0; j < 8; ++j) {
                int k = kbase + j;
                float d2e = __fadd_rn(__fadd_rn(rv, __fmul_rn(-2.0f, aa[j])), csq[k]);
                unsigned long long pk =
                    ((unsigned long long)ford(d2e) << 32) | (unsigned)k;
                if (pk < bw) bw = pk;
            }
            #pragma unroll
            for (int off = 16; off > 0; off >>= 1) {
                unsigned long long o = __shfl_xor_sync(0xffffffffu, bw, off);
                if (o < bw) bw = o;
            }
            if (lane == 0) bestk[lrow] = bw;
        }
        __syncwarp();

        // ---- outputs: one-hot (zero stcs + poke) + recon = prev + C (default st) ----
        #pragma unroll 1
        for (int g = 0; g < 2; ++g) {
            int bx[4];
            float4 cv[4];
            #pragma unroll
            for (int r4 = 0; r4 < 4; ++r4) {
                int lrow = wid * 8 + g * 4 + r4;
                bx[r4] = (int)(bestk[lrow] & 0xffffffffull);
                cv[r4] = __ldg((const float4*)(C + (size_t)bx[r4] * DD) + lane);
            }
            const float4 z4 = make_float4(0.f, 0.f, 0.f, 0.f);
            #pragma unroll
            for (int r4 = 0; r4 < 4; ++r4) {
                int n = rowBase + wid * 8 + g * 4 + r4;
                float4* crow =
                    (float4*)(codes + (size_t)n * (MM * KK) + (size_t)stage * KK);
                __stcs(crow + lane, z4);
                __stcs(crow + lane + 32, z4);
            }
            __syncwarp();
            if (lane < 4) {
                int n = rowBase + wid * 8 + g * 4 + lane;
                codes[(size_t)n * (MM * KK) + (size_t)stage * KK + bx[lane]] = 1.0f;
            }
            #pragma unroll
            for (int r4 = 0; r4 < 4; ++r4) {
                int lrow = wid * 8 + g * 4 + r4;
                int n    = rowBase + lrow;
                float4 pp = prev ? __ldg((const float4*)(prev + (size_t)n * DD) + lane)
                                 : make_float4(0.f, 0.f, 0.f, 0.f);
                float4 v;
                v.x = __fadd_rn(pp.x, cv[r4].x);
                v.y = __fadd_rn(pp.y, cv[r4].y);
                v.z = __fadd_rn(pp.z, cv[r4].z);
                v.w = __fadd_rn(pp.w, cv[r4].w);
                // default store: keep L2-resident for next stage's prev reads
                ((float4*)(side + ((size_t)stage * NN + n) * DD))[lane] = v;
                if (last) __stcs((float4*)(xrecon + (size_t)n * DD) + lane, v);
            }
        }
        __syncthreads();   // RB/CB reuse + side visibility next stage
    }
}

extern "C" void kernel_launch(void* const* d_in, const int* in_sizes, int n_in,
                              void* d_out, int out_size)
{
    (void)in_sizes; (void)n_in; (void)out_size;
    const float* x  = (const float*)d_in[0];            // (N, D)
    const float* cb = (const float*)d_in[1];            // (M, K, D)

    float* out    = (float*)d_out;
    float* xrecon = out;                                // (N, D)
    float* codes  = out + (size_t)NN * DD;              // (N, M, K)
    float* side   = codes + (size_t)NN * MM * KK;       // (M, N, D)

    cudaFuncSetAttribute(rq_fused_kernel,
                         cudaFuncAttributeMaxDynamicSharedMemorySize, SM_BYTES);

    csq_prep_kernel<<<MM, KK>>>(cb);
    cbt_prep_kernel<<<dim3(MM, DD), KK>>>(cb);
    cbh_prep_kernel<<<MM, KK>>>(cb);

    rq_fused_kernel<<<NN / BM, THREADS, SM_BYTES>>>(x, cb, codes, side, xrecon);
}